// round 1
// baseline (speedup 1.0000x reference)
#include <cuda_runtime.h>
#include <math.h>

#define NT 256

// ---- shared memory layout (float offsets) ----
#define OFF_CWT   0        // [8][16][64]  chart_w transposed (c, l, h)   8192
#define OFF_TEXWT 8192     // [16][64]     tex_w transposed (l, h)        1024
#define OFF_W1T   9216     // [64][64]     w1 transposed (k, o)           4096
#define OFF_W2T   13312    // [64][32]     w2 transposed (k, o)           2048
#define OFF_CB    15360    // [8][64]      chart_b                         512
#define OFF_CEN   15872    // [8][16]      centers                         128
#define OFF_RW    16000    // [8][16]      router_w                        128
#define OFF_RB    16128    // [8]          router_b                          8
#define OFF_TEXB  16136    // [64]                                          64
#define OFF_LNG   16200    // [64]                                          64
#define OFF_LNB   16264    // [64]                                          64
#define OFF_B1    16328    // [64]                                          64
#define OFF_B2    16392    // [32]                                          32
// per-thread staging, [dim][NT] layout (bank-conflict-free)
#define OFF_ZG    16424    // [16][NT]                                    4096
#define OFF_ZT    20520    // [16][NT]                                    4096
#define OFF_GS    24616    // [64][NT]                                   16384
#define SMEM_FLOATS 41000  // 164000 bytes

__device__ __forceinline__ float gelu_exact(float x) {
    return x * normcdff(x);
}

__global__ __launch_bounds__(NT)
void topo_decoder_kernel(
    const float* __restrict__ z_geo, const float* __restrict__ z_tex,
    const float* __restrict__ chart_w, const float* __restrict__ chart_b,
    const float* __restrict__ router_w, const float* __restrict__ router_b,
    const float* __restrict__ centers,
    const float* __restrict__ tex_w, const float* __restrict__ tex_b,
    const float* __restrict__ ln_g, const float* __restrict__ ln_b,
    const float* __restrict__ w1, const float* __restrict__ b1,
    const float* __restrict__ w2, const float* __restrict__ b2,
    float* __restrict__ out, int B)
{
    extern __shared__ float sm[];
    const int tid = threadIdx.x;

    // ---- cooperative weight staging (transposed for contiguous h-dim) ----
    for (int i = tid; i < 8192; i += NT) {
        int c = i >> 10, r = i & 1023, hh = r >> 4, l = r & 15;
        sm[OFF_CWT + (c << 10) + (l << 6) + hh] = chart_w[i];
    }
    for (int i = tid; i < 1024; i += NT) {
        int hh = i >> 4, l = i & 15;
        sm[OFF_TEXWT + l * 64 + hh] = tex_w[i];
    }
    for (int i = tid; i < 4096; i += NT) {
        int o = i >> 6, k = i & 63;
        sm[OFF_W1T + k * 64 + o] = w1[i];
    }
    for (int i = tid; i < 2048; i += NT) {
        int o = i >> 6, k = i & 63;
        sm[OFF_W2T + k * 32 + o] = w2[i];
    }
    for (int i = tid; i < 512; i += NT) sm[OFF_CB + i] = chart_b[i];
    if (tid < 128) { sm[OFF_CEN + tid] = centers[tid]; sm[OFF_RW + tid] = router_w[tid]; }
    if (tid < 64)  { sm[OFF_TEXB + tid] = tex_b[tid]; sm[OFF_LNG + tid] = ln_g[tid];
                     sm[OFF_LNB + tid] = ln_b[tid];   sm[OFF_B1 + tid]  = b1[tid]; }
    if (tid < 32)  sm[OFF_B2 + tid] = b2[tid];
    if (tid < 8)   sm[OFF_RB + tid] = router_b[tid];
    __syncthreads();

    const int row = blockIdx.x * NT + tid;
    if (row >= B) return;

    // ---- load latents ----
    float zg[16], zt[16];
    {
        const float4* p = (const float4*)(z_geo + (size_t)row * 16);
        #pragma unroll
        for (int q = 0; q < 4; ++q) {
            float4 v = p[q];
            zg[q*4+0] = v.x; zg[q*4+1] = v.y; zg[q*4+2] = v.z; zg[q*4+3] = v.w;
        }
        const float4* p2 = (const float4*)(z_tex + (size_t)row * 16);
        #pragma unroll
        for (int q = 0; q < 4; ++q) {
            float4 v = p2[q];
            zt[q*4+0] = v.x; zt[q*4+1] = v.y; zt[q*4+2] = v.z; zt[q*4+3] = v.w;
        }
    }

    float z_sq = 0.f;
    #pragma unroll
    for (int l = 0; l < 16; ++l) z_sq = fmaf(zg[l], zg[l], z_sq);
    const float one_minus = 1.0f - z_sq;
    const float tau = fmaxf(2.0f * fmaxf(one_minus, 0.001f), 0.01f);
    const float inv_tau = 1.0f / tau;

    // ---- router scores ----
    float w[8];
    float mx = -1e30f;
    #pragma unroll
    for (int c = 0; c < 8; ++c) {
        float ds = 0.f, cs = 0.f, dr = 0.f;
        #pragma unroll
        for (int l = 0; l < 16; ++l) {
            float cv = sm[OFF_CEN + c * 16 + l];
            float d  = zg[l] - cv;
            ds = fmaf(d, d, ds);
            cs = fmaf(cv, cv, cs);
            dr = fmaf(zg[l], sm[OFF_RW + c * 16 + l], dr);
        }
        float denom = one_minus * (1.0f - cs);
        float arg = fmaf(2.0f * ds, 1.0f / (denom + 0.001f), 1.0f);
        arg = fmaxf(arg, 1.0f + 0.001f);
        float dist = acoshf(arg);
        float s = (-dist + 0.1f * (dr + sm[OFF_RB + c])) * inv_tau;
        w[c] = s;
        mx = fmaxf(mx, s);
    }
    float ssum = 0.f;
    #pragma unroll
    for (int c = 0; c < 8; ++c) { w[c] = expf(w[c] - mx); ssum += w[c]; }
    const float inv_sum = 1.0f / ssum;
    #pragma unroll
    for (int c = 0; c < 8; ++c) w[c] *= inv_sum;

    // write router weights
    {
        float* rout = out + (size_t)B * 32 + (size_t)row * 8;
        float4 v0 = make_float4(w[0], w[1], w[2], w[3]);
        float4 v1 = make_float4(w[4], w[5], w[6], w[7]);
        ((float4*)rout)[0] = v0;
        ((float4*)rout)[1] = v1;
    }

    // stage per-thread latents (bank-conflict-free columns)
    #pragma unroll
    for (int l = 0; l < 16; ++l) {
        sm[OFF_ZG + l * NT + tid] = zg[l];
        sm[OFF_ZT + l * NT + tid] = zt[l];
    }

    // ---- h = tex_b + sum_c w_c*(chart_w[c]@zg + chart_b[c]) + tex_w@zt ----
    float h[64];
    #pragma unroll
    for (int i = 0; i < 64; ++i) h[i] = sm[OFF_TEXB + i];

    // chart biases (unrolled, w[c] in registers)
    #pragma unroll
    for (int c = 0; c < 8; ++c) {
        float wc = w[c];
        #pragma unroll
        for (int q = 0; q < 16; ++q) {
            float4 bv = *(const float4*)&sm[OFF_CB + c * 64 + q * 4];
            h[q*4+0] = fmaf(wc, bv.x, h[q*4+0]);
            h[q*4+1] = fmaf(wc, bv.y, h[q*4+1]);
            h[q*4+2] = fmaf(wc, bv.z, h[q*4+2]);
            h[q*4+3] = fmaf(wc, bv.w, h[q*4+3]);
        }
    }

    // tex projection
    #pragma unroll 1
    for (int l = 0; l < 16; ++l) {
        float coef = sm[OFF_ZT + l * NT + tid];
        const float4* wr = (const float4*)&sm[OFF_TEXWT + l * 64];
        #pragma unroll
        for (int q = 0; q < 16; ++q) {
            float4 v = wr[q];
            h[q*4+0] = fmaf(coef, v.x, h[q*4+0]);
            h[q*4+1] = fmaf(coef, v.y, h[q*4+1]);
            h[q*4+2] = fmaf(coef, v.z, h[q*4+2]);
            h[q*4+3] = fmaf(coef, v.w, h[q*4+3]);
        }
    }

    // chart projections (c unrolled so w[c] stays in a register; l runtime loop)
    #pragma unroll
    for (int c = 0; c < 8; ++c) {
        float wc = w[c];
        #pragma unroll 1
        for (int l = 0; l < 16; ++l) {
            float coef = wc * sm[OFF_ZG + l * NT + tid];
            const float4* wr = (const float4*)&sm[OFF_CWT + c * 1024 + l * 64];
            #pragma unroll
            for (int q = 0; q < 16; ++q) {
                float4 v = wr[q];
                h[q*4+0] = fmaf(coef, v.x, h[q*4+0]);
                h[q*4+1] = fmaf(coef, v.y, h[q*4+1]);
                h[q*4+2] = fmaf(coef, v.z, h[q*4+2]);
                h[q*4+3] = fmaf(coef, v.w, h[q*4+3]);
            }
        }
    }

    // ---- LayerNorm + GELU, stage to smem ----
    float s1 = 0.f;
    #pragma unroll
    for (int i = 0; i < 64; ++i) s1 += h[i];
    const float mu = s1 * (1.0f / 64.0f);
    float s2 = 0.f;
    #pragma unroll
    for (int i = 0; i < 64; ++i) { float d = h[i] - mu; s2 = fmaf(d, d, s2); }
    const float rstd = rsqrtf(s2 * (1.0f / 64.0f) + 1e-5f);
    #pragma unroll
    for (int i = 0; i < 64; ++i) {
        float hn = (h[i] - mu) * rstd * sm[OFF_LNG + i] + sm[OFF_LNB + i];
        sm[OFF_GS + i * NT + tid] = gelu_exact(hn);
    }

    // ---- h1 = gelu(g @ w1^T + b1) ----
    float a1[64];
    #pragma unroll
    for (int i = 0; i < 64; ++i) a1[i] = 0.f;
    #pragma unroll 1
    for (int k = 0; k < 64; ++k) {
        float gk = sm[OFF_GS + k * NT + tid];
        const float4* wr = (const float4*)&sm[OFF_W1T + k * 64];
        #pragma unroll
        for (int q = 0; q < 16; ++q) {
            float4 v = wr[q];
            a1[q*4+0] = fmaf(gk, v.x, a1[q*4+0]);
            a1[q*4+1] = fmaf(gk, v.y, a1[q*4+1]);
            a1[q*4+2] = fmaf(gk, v.z, a1[q*4+2]);
            a1[q*4+3] = fmaf(gk, v.w, a1[q*4+3]);
        }
    }
    #pragma unroll
    for (int i = 0; i < 64; ++i) {
        float v = a1[i] + sm[OFF_B1 + i];
        sm[OFF_GS + i * NT + tid] = gelu_exact(v);
    }

    // ---- x_hat = h1 @ w2^T + b2 ----
    float a2[32];
    #pragma unroll
    for (int i = 0; i < 32; ++i) a2[i] = 0.f;
    #pragma unroll 1
    for (int k = 0; k < 64; ++k) {
        float hk = sm[OFF_GS + k * NT + tid];
        const float4* wr = (const float4*)&sm[OFF_W2T + k * 32];
        #pragma unroll
        for (int q = 0; q < 8; ++q) {
            float4 v = wr[q];
            a2[q*4+0] = fmaf(hk, v.x, a2[q*4+0]);
            a2[q*4+1] = fmaf(hk, v.y, a2[q*4+1]);
            a2[q*4+2] = fmaf(hk, v.z, a2[q*4+2]);
            a2[q*4+3] = fmaf(hk, v.w, a2[q*4+3]);
        }
    }
    {
        float4* xo = (float4*)(out + (size_t)row * 32);
        #pragma unroll
        for (int q = 0; q < 8; ++q) {
            float4 v = make_float4(a2[q*4+0] + sm[OFF_B2 + q*4+0],
                                   a2[q*4+1] + sm[OFF_B2 + q*4+1],
                                   a2[q*4+2] + sm[OFF_B2 + q*4+2],
                                   a2[q*4+3] + sm[OFF_B2 + q*4+3]);
            xo[q] = v;
        }
    }
}

extern "C" void kernel_launch(void* const* d_in, const int* in_sizes, int n_in,
                              void* d_out, int out_size) {
    const float* z_geo    = (const float*)d_in[0];
    const float* z_tex    = (const float*)d_in[1];
    const float* chart_w  = (const float*)d_in[2];
    const float* chart_b  = (const float*)d_in[3];
    const float* router_w = (const float*)d_in[4];
    const float* router_b = (const float*)d_in[5];
    const float* centers  = (const float*)d_in[6];
    const float* tex_w    = (const float*)d_in[7];
    const float* tex_b    = (const float*)d_in[8];
    const float* ln_g     = (const float*)d_in[9];
    const float* ln_b     = (const float*)d_in[10];
    const float* w1       = (const float*)d_in[11];
    const float* b1       = (const float*)d_in[12];
    const float* w2       = (const float*)d_in[13];
    const float* b2       = (const float*)d_in[14];
    float* out = (float*)d_out;

    const int B = in_sizes[0] / 16;
    const size_t smem_bytes = (size_t)SMEM_FLOATS * sizeof(float);
    cudaFuncSetAttribute(topo_decoder_kernel,
                         cudaFuncAttributeMaxDynamicSharedMemorySize,
                         (int)smem_bytes);
    const int grid = (B + NT - 1) / NT;
    topo_decoder_kernel<<<grid, NT, smem_bytes>>>(
        z_geo, z_tex, chart_w, chart_b, router_w, router_b, centers,
        tex_w, tex_b, ln_g, ln_b, w1, b1, w2, b2, out, B);
}